// round 1
// baseline (speedup 1.0000x reference)
#include <cuda_runtime.h>
#include <cstdint>

#define B_    64
#define N_    128
#define DIN_  64
#define DOUT_ 64

// Scratch: per-(b,j) list of k with A[b,k,j] != 0  (values are exactly 0/1)
__device__ unsigned char g_idx[B_ * N_ * N_];   // [ (b*N + j) * N + c ]
__device__ int           g_cnt[B_ * N_];

// ---------------------------------------------------------------------------
// Kernel A: build column-wise nonzero lists of A. 64 blocks x 128 threads.
// Thread j scans column j of A[b] (coalesced across j for each k).
// ---------------------------------------------------------------------------
__global__ void build_cols_kernel(const float* __restrict__ A) {
    int b = blockIdx.x;
    int j = threadIdx.x;                     // 0..127
    const float* Ab = A + (size_t)b * N_ * N_;
    unsigned char* lst = g_idx + ((size_t)(b * N_ + j)) * N_;
    int cnt = 0;
    #pragma unroll 4
    for (int k = 0; k < N_; ++k) {
        float v = Ab[k * N_ + j];
        if (v != 0.0f) lst[cnt++] = (unsigned char)k;
    }
    g_cnt[b * N_ + j] = cnt;
}

// ---------------------------------------------------------------------------
// Kernel B: one CTA per (b,i).
//   step 1: tX[k][e] = sum_d X[b,i,k,d] * W[d,e] + bias[e]   (smem, fp32)
//   step 2: out[b,i,j][e] = sum_{k in nz(b,j)} tX[k][e]      (sparse adds)
// 256 threads: group g = t/16 (16 groups), lane lt = t%16 (float4 e-chunk).
// ---------------------------------------------------------------------------
__global__ __launch_bounds__(256, 2)
void ngnn_main_kernel(const float* __restrict__ X,
                      const float* __restrict__ W,
                      const float* __restrict__ bias,
                      float* __restrict__ out) {
    extern __shared__ float smem[];
    float* Ws  = smem;                 // 64*64   = 4096 floats (16 KB)
    float* Xs  = Ws + 4096;            // 128*64  = 8192 floats (32 KB)
    float* tXs = Xs + 8192;            // 128*64  = 8192 floats (32 KB)
    int* s_cnt = (int*)(tXs + 8192);                     // 128 ints
    unsigned char* s_idx = (unsigned char*)(s_cnt + 128); // 128*128 bytes

    const int i = blockIdx.x;
    const int b = blockIdx.y;
    const int t = threadIdx.x;

    // ---- cooperative loads (all coalesced float4 / uint4) ----
    {
        const float4* W4 = (const float4*)W;          // 1024 float4
        float4* Ws4 = (float4*)Ws;
        #pragma unroll
        for (int r = 0; r < 4; ++r) Ws4[t + r * 256] = W4[t + r * 256];

        const float4* X4 = (const float4*)(X + ((size_t)(b * N_ + i)) * N_ * DIN_); // 2048 f4
        float4* Xs4 = (float4*)Xs;
        #pragma unroll
        for (int r = 0; r < 8; ++r) Xs4[t + r * 256] = X4[t + r * 256];

        if (t < 128) s_cnt[t] = g_cnt[b * N_ + t];
        const uint4* gi4 = (const uint4*)(g_idx + (size_t)b * N_ * N_); // 1024 uint4
        uint4* si4 = (uint4*)s_idx;
        #pragma unroll
        for (int r = 0; r < 4; ++r) si4[t + r * 256] = gi4[t + r * 256];
    }
    __syncthreads();

    const int lt = t & 15;   // e float4-chunk: e in [4*lt, 4*lt+4)
    const int g  = t >> 4;   // 0..15

    const float4 bias4 = ((const float4*)bias)[lt];

    // ---- step 1: register tile 4 k-rows x 4 e-cols per thread, 2 passes ----
    #pragma unroll
    for (int p = 0; p < 2; ++p) {
        const int kb = (p * 16 + g) * 4;           // covers k = 0..127
        float4 a0 = bias4, a1 = bias4, a2 = bias4, a3 = bias4;
        const float* x0p = Xs + (kb + 0) * 64;
        const float* x1p = Xs + (kb + 1) * 64;
        const float* x2p = Xs + (kb + 2) * 64;
        const float* x3p = Xs + (kb + 3) * 64;
        const float4* Wrow = ((const float4*)Ws) + lt;
        #pragma unroll
        for (int d = 0; d < 64; ++d) {
            const float4 w = Wrow[d * 16];
            const float x0 = x0p[d];
            const float x1 = x1p[d];
            const float x2 = x2p[d];
            const float x3 = x3p[d];
            a0.x += x0 * w.x; a0.y += x0 * w.y; a0.z += x0 * w.z; a0.w += x0 * w.w;
            a1.x += x1 * w.x; a1.y += x1 * w.y; a1.z += x1 * w.z; a1.w += x1 * w.w;
            a2.x += x2 * w.x; a2.y += x2 * w.y; a2.z += x2 * w.z; a2.w += x2 * w.w;
            a3.x += x3 * w.x; a3.y += x3 * w.y; a3.z += x3 * w.z; a3.w += x3 * w.w;
        }
        float4* tX4 = (float4*)tXs;
        tX4[(kb + 0) * 16 + lt] = a0;
        tX4[(kb + 1) * 16 + lt] = a1;
        tX4[(kb + 2) * 16 + lt] = a2;
        tX4[(kb + 3) * 16 + lt] = a3;
    }
    __syncthreads();

    // ---- step 2: sparse column-sum of tX rows ----
    float* outp = out + ((size_t)(b * N_ + i)) * N_ * DOUT_;
    const float4* tX4 = (const float4*)tXs;
    #pragma unroll
    for (int jp = 0; jp < 8; ++jp) {
        const int j = jp * 16 + g;
        const int cnt = s_cnt[j];
        const unsigned char* lst = s_idx + j * N_;
        float4 acc = make_float4(0.f, 0.f, 0.f, 0.f);
        for (int c = 0; c < cnt; ++c) {
            const int k = lst[c];
            const float4 v = tX4[k * 16 + lt];
            acc.x += v.x; acc.y += v.y; acc.z += v.z; acc.w += v.w;
        }
        ((float4*)outp)[j * 16 + lt] = acc;
    }
}

// ---------------------------------------------------------------------------
extern "C" void kernel_launch(void* const* d_in, const int* in_sizes, int n_in,
                              void* d_out, int out_size) {
    const float* X    = (const float*)d_in[0];  // [B,N,N,DIN]
    const float* A    = (const float*)d_in[1];  // [B,N,N]
    const float* W    = (const float*)d_in[2];  // [DIN,DOUT]
    const float* bias = (const float*)d_in[3];  // [DOUT]
    float* out = (float*)d_out;                 // [B,N,N,DOUT]

    build_cols_kernel<<<B_, N_>>>(A);

    const int smem_bytes = (4096 + 8192 + 8192) * 4 + 128 * 4 + 128 * 128; // 98816
    static bool attr_set = false;
    // cudaFuncSetAttribute is idempotent and not a stream op; safe under capture.
    cudaFuncSetAttribute(ngnn_main_kernel,
                         cudaFuncAttributeMaxDynamicSharedMemorySize, smem_bytes);
    (void)attr_set;

    dim3 grid(N_, B_);
    ngnn_main_kernel<<<grid, 256, smem_bytes>>>(X, W, bias, out);
}